// round 11
// baseline (speedup 1.0000x reference)
#include <cuda_runtime.h>
#include <cuda_fp16.h>
#include <cstdint>

#define Bn 4
#define Tn 1024
#define Sn 1024
#define Hn 16
#define Dn 64
#define RS (Hn*Dn)
#define MQc 128              // queries per CTA
#define NKC 64               // keys per chunk
#define NCH (Sn/NKC)         // 16
#define NT 128

// per-(b,h,chunk): K fragments 8KB + V fragments 8KB, MMA-fragment-direct order
#define CH_B 16384
#define OFF_V 8192
__device__ __align__(128) unsigned char g_kv[(size_t)Bn*Hn*NCH*CH_B];   // 16 MB

// exp(x) = ex2(x * log2e); fold log2e/8 into Q scale
#define QSCALE 0.18033688011112042f

__device__ __forceinline__ void mma_f16(float* c, const uint32_t* a, uint32_t b0, uint32_t b1) {
    asm volatile("mma.sync.aligned.m16n8k16.row.col.f32.f16.f16.f32 "
        "{%0,%1,%2,%3}, {%4,%5,%6,%7}, {%8,%9}, {%0,%1,%2,%3};"
        : "+f"(c[0]), "+f"(c[1]), "+f"(c[2]), "+f"(c[3])
        : "r"(a[0]), "r"(a[1]), "r"(a[2]), "r"(a[3]), "r"(b0), "r"(b1));
}
__device__ __forceinline__ uint32_t packh2(float a, float b) {
    __half2 h = __floats2half2_rn(a, b);
    return *(uint32_t*)&h;
}
__device__ __forceinline__ float ex2f(float x) {
    float r;
    asm("ex2.approx.f32 %0, %1;" : "=f"(r) : "f"(x));
    return r;
}

// =================== prep: fp32 K/V -> fp16 fragment-direct blocks ===================
// K block (jj,ks): lane l holds B-frag 16B for QK mma (keys jj*16.., dims ks*16..)
// V block (kg,p):  lane l holds B-frag 16B for PV mma (keys kg*16.., dims p*16..)
__global__ __launch_bounds__(128)
void prep_kernel(const float* __restrict__ k, const float* __restrict__ v) {
    const int c = blockIdx.x, h = blockIdx.y, b = blockIdx.z, tid = threadIdx.x;
    const float* kb = k + (((size_t)b * Sn + c * NKC) * Hn + h) * Dn;
    const float* vb = v + (((size_t)b * Sn + c * NKC) * Hn + h) * Dn;
    unsigned char* dst = g_kv + (size_t)((b * Hn + h) * NCH + c) * CH_B;
    #pragma unroll
    for (int i = 0; i < 4; i++) {
        int slot = tid + i * 128;
        int blk = slot >> 5, l = slot & 31;
        int m0 = l & 3, n8 = l >> 2;
        {   // K fragment: blk = jj*4 + ks
            int jj = blk >> 2, ks = blk & 3;
            int j0 = jj * 16, d0 = ks * 16 + 2 * m0;
            const float* kr0 = kb + (size_t)(j0 + n8) * RS;
            const float* kr1 = kr0 + 8 * RS;
            uint4 u;
            u.x = packh2(kr0[d0],     kr0[d0 + 1]);
            u.y = packh2(kr0[d0 + 8], kr0[d0 + 9]);
            u.z = packh2(kr1[d0],     kr1[d0 + 1]);
            u.w = packh2(kr1[d0 + 8], kr1[d0 + 9]);
            *(uint4*)(dst + slot * 16) = u;
        }
        {   // V fragment: blk = kg*4 + p
            int kg = blk >> 2, p = blk & 3;
            int key0 = kg * 16 + 2 * m0, dim0 = p * 16 + n8;
            const float* v0 = vb + (size_t)key0 * RS + dim0;
            uint4 u;
            u.x = packh2(v0[0],          v0[RS]);
            u.y = packh2(v0[8 * RS],     v0[9 * RS]);
            u.z = packh2(v0[8],          v0[RS + 8]);
            u.w = packh2(v0[8 * RS + 8], v0[9 * RS + 8]);
            *(uint4*)(dst + OFF_V + slot * 16) = u;
        }
    }
}

// =================== main attention kernel: NO smem, NO syncthreads ===================
__global__ __launch_bounds__(NT, 4)
void attn_main(const float* __restrict__ q,
               float* __restrict__ out_attn, float* __restrict__ out_probs) {
    const int tid = threadIdx.x, lane = tid & 31, w = tid >> 5;
    const int band = w * 32;                  // warp owns 32 query rows
    const int t0 = blockIdx.x * MQc, h = blockIdx.y, b = blockIdx.z;
    const int g = lane >> 2, t = lane & 3;

    const unsigned char* kvb = g_kv + (size_t)((b * Hn + h) * NCH) * CH_B;
    const float* qbase = q + (((size_t)b * Tn + t0 + band + g) * Hn + h) * Dn;

    // ---- Q fp16 fragments, 2 m-tiles, scale (log2e/8) folded in ----
    uint32_t qf[2][4][4];
    #pragma unroll
    for (int m = 0; m < 2; m++) {
        const float* qrG = qbase + (size_t)(m * 16) * RS;
        const float* qrH = qrG + 8 * RS;
        #pragma unroll
        for (int ks = 0; ks < 4; ks++) {
            float2 f0 = *(const float2*)(qrG + ks * 16 + 2 * t);
            float2 f1 = *(const float2*)(qrH + ks * 16 + 2 * t);
            float2 f2 = *(const float2*)(qrG + ks * 16 + 2 * t + 8);
            float2 f3 = *(const float2*)(qrH + ks * 16 + 2 * t + 8);
            qf[m][ks][0] = packh2(f0.x * QSCALE, f0.y * QSCALE);
            qf[m][ks][1] = packh2(f1.x * QSCALE, f1.y * QSCALE);
            qf[m][ks][2] = packh2(f2.x * QSCALE, f2.y * QSCALE);
            qf[m][ks][3] = packh2(f3.x * QSCALE, f3.y * QSCALE);
        }
    }

    float sG[2] = {0.f, 0.f}, sH[2] = {0.f, 0.f};

    // ================= Pass A: rowsums (pure LDG.128 fragments) =================
    for (int c = 0; c < NCH; c++) {
        const uint4* kf = (const uint4*)(kvb + (size_t)c * CH_B) + lane;
        #pragma unroll
        for (int jj = 0; jj < 4; jj++) {
            float S[2][2][4];
            #pragma unroll
            for (int m = 0; m < 2; m++)
                #pragma unroll
                for (int i = 0; i < 2; i++)
                    { S[m][i][0] = 0.f; S[m][i][1] = 0.f; S[m][i][2] = 0.f; S[m][i][3] = 0.f; }
            #pragma unroll
            for (int ks = 0; ks < 4; ks++) {
                uint4 kv = kf[(jj * 4 + ks) * 32];
                mma_f16(S[0][0], qf[0][ks], kv.x, kv.y);
                mma_f16(S[0][1], qf[0][ks], kv.z, kv.w);
                mma_f16(S[1][0], qf[1][ks], kv.x, kv.y);
                mma_f16(S[1][1], qf[1][ks], kv.z, kv.w);
            }
            #pragma unroll
            for (int m = 0; m < 2; m++)
                #pragma unroll
                for (int i = 0; i < 2; i++) {
                    sG[m] += ex2f(S[m][i][0]) + ex2f(S[m][i][1]);
                    sH[m] += ex2f(S[m][i][2]) + ex2f(S[m][i][3]);
                }
        }
    }
    #pragma unroll
    for (int m = 0; m < 2; m++) {
        sG[m] += __shfl_xor_sync(0xffffffffu, sG[m], 1);
        sG[m] += __shfl_xor_sync(0xffffffffu, sG[m], 2);
        sH[m] += __shfl_xor_sync(0xffffffffu, sH[m], 1);
        sH[m] += __shfl_xor_sync(0xffffffffu, sH[m], 2);
    }
    const float iG0 = 1.f / sG[0], iH0 = 1.f / sH[0];
    const float iG1 = 1.f / sG[1], iH1 = 1.f / sH[1];

    // ================= Pass B: probs + PV =================
    float O[2][8][4];
    #pragma unroll
    for (int m = 0; m < 2; m++)
        #pragma unroll
        for (int i = 0; i < 8; i++)
            { O[m][i][0] = 0.f; O[m][i][1] = 0.f; O[m][i][2] = 0.f; O[m][i][3] = 0.f; }

    float* prow0G = out_probs + (((size_t)b * Tn + t0 + band + g) * Hn + h) * Sn;
    float* prow0H = prow0G + (size_t)8 * Hn * Sn;
    float* prow1G = prow0G + (size_t)16 * Hn * Sn;
    float* prow1H = prow0G + (size_t)24 * Hn * Sn;

    // STG.128 column mapping after pair exchange: t -> 0,8,4,12
    const int colOff = 2 * t + ((t & 1) ? 6 : 0);
    const bool todd = (t & 1);

    for (int c = 0; c < NCH; c++) {
        const uint4* kf = (const uint4*)(kvb + (size_t)c * CH_B) + lane;
        const uint4* vf = (const uint4*)(kvb + (size_t)c * CH_B + OFF_V) + lane;

        #pragma unroll
        for (int jj = 0; jj < 4; jj++) {
            float S[2][2][4];
            #pragma unroll
            for (int m = 0; m < 2; m++)
                #pragma unroll
                for (int i = 0; i < 2; i++)
                    { S[m][i][0] = 0.f; S[m][i][1] = 0.f; S[m][i][2] = 0.f; S[m][i][3] = 0.f; }
            #pragma unroll
            for (int ks = 0; ks < 4; ks++) {
                uint4 kv = kf[(jj * 4 + ks) * 32];
                mma_f16(S[0][0], qf[0][ks], kv.x, kv.y);
                mma_f16(S[0][1], qf[0][ks], kv.z, kv.w);
                mma_f16(S[1][0], qf[1][ks], kv.x, kv.y);
                mma_f16(S[1][1], qf[1][ks], kv.z, kv.w);
            }

            const int col = c * 64 + jj * 16;
            uint32_t a[2][4];

            // --- per row-half: exp, normalize, shuffled STG.128, pack A-frag ---
            {   // m0, G rows
                float x0 = ex2f(S[0][0][0]) * iG0, x1 = ex2f(S[0][0][1]) * iG0;
                float x2 = ex2f(S[0][1][0]) * iG0, x3 = ex2f(S[0][1][1]) * iG0;
                a[0][0] = packh2(x0, x1); a[0][2] = packh2(x2, x3);
                float s0 = todd ? x0 : x2, s1 = todd ? x1 : x3;
                float r0 = __shfl_xor_sync(0xffffffffu, s0, 1);
                float r1 = __shfl_xor_sync(0xffffffffu, s1, 1);
                float4 o = todd ? make_float4(r0, r1, x2, x3) : make_float4(x0, x1, r0, r1);
                __stcs((float4*)(prow0G + col + colOff), o);
            }
            {   // m0, H rows
                float x0 = ex2f(S[0][0][2]) * iH0, x1 = ex2f(S[0][0][3]) * iH0;
                float x2 = ex2f(S[0][1][2]) * iH0, x3 = ex2f(S[0][1][3]) * iH0;
                a[0][1] = packh2(x0, x1); a[0][3] = packh2(x2, x3);
                float s0 = todd ? x0 : x2, s1 = todd ? x1 : x3;
                float r0 = __shfl_xor_sync(0xffffffffu, s0, 1);
                float r1 = __shfl_xor_sync(0xffffffffu, s1, 1);
                float4 o = todd ? make_float4(r0, r1, x2, x3) : make_float4(x0, x1, r0, r1);
                __stcs((float4*)(prow0H + col + colOff), o);
            }
            {   // m1, G rows
                float x0 = ex2f(S[1][0][0]) * iG1, x1 = ex2f(S[1][0][1]) * iG1;
                float x2 = ex2f(S[1][1][0]) * iG1, x3 = ex2f(S[1][1][1]) * iG1;
                a[1][0] = packh2(x0, x1); a[1][2] = packh2(x2, x3);
                float s0 = todd ? x0 : x2, s1 = todd ? x1 : x3;
                float r0 = __shfl_xor_sync(0xffffffffu, s0, 1);
                float r1 = __shfl_xor_sync(0xffffffffu, s1, 1);
                float4 o = todd ? make_float4(r0, r1, x2, x3) : make_float4(x0, x1, r0, r1);
                __stcs((float4*)(prow1G + col + colOff), o);
            }
            {   // m1, H rows
                float x0 = ex2f(S[1][0][2]) * iH1, x1 = ex2f(S[1][0][3]) * iH1;
                float x2 = ex2f(S[1][1][2]) * iH1, x3 = ex2f(S[1][1][3]) * iH1;
                a[1][1] = packh2(x0, x1); a[1][3] = packh2(x2, x3);
                float s0 = todd ? x0 : x2, s1 = todd ? x1 : x3;
                float r0 = __shfl_xor_sync(0xffffffffu, s0, 1);
                float r1 = __shfl_xor_sync(0xffffffffu, s1, 1);
                float4 o = todd ? make_float4(r0, r1, x2, x3) : make_float4(x0, x1, r0, r1);
                __stcs((float4*)(prow1H + col + colOff), o);
            }

            // --- PV: fragment-direct V loads ---
            #pragma unroll
            for (int p = 0; p < 4; p++) {
                uint4 vv = vf[(jj * 4 + p) * 32];
                mma_f16(O[0][2 * p],     a[0], vv.x, vv.y);
                mma_f16(O[0][2 * p + 1], a[0], vv.z, vv.w);
                mma_f16(O[1][2 * p],     a[1], vv.x, vv.y);
                mma_f16(O[1][2 * p + 1], a[1], vv.z, vv.w);
            }
        }
    }

    // ================= output (P pre-normalized; warp owns all keys) =================
    #pragma unroll
    for (int m = 0; m < 2; m++) {
        float* oarG = out_attn + (((size_t)b * Tn + t0 + band + m * 16 + g) * Hn + h) * Dn;
        float* oarH = oarG + 8 * RS;
        #pragma unroll
        for (int nd = 0; nd < 8; nd++) {
            *(float2*)(oarG + nd * 8 + 2 * t) = make_float2(O[m][nd][0], O[m][nd][1]);
            *(float2*)(oarH + nd * 8 + 2 * t) = make_float2(O[m][nd][2], O[m][nd][3]);
        }
    }
}

extern "C" void kernel_launch(void* const* d_in, const int* in_sizes, int n_in,
                              void* d_out, int out_size) {
    const float* q = (const float*)d_in[0];
    const float* k = (const float*)d_in[1];
    const float* v = (const float*)d_in[2];
    float* out_attn  = (float*)d_out;
    float* out_probs = (float*)d_out + (size_t)Bn * Tn * Hn * Dn;

    dim3 pgrid(NCH, Hn, Bn);
    prep_kernel<<<pgrid, 128>>>(k, v);

    dim3 grid(Tn / MQc, Hn, Bn);   // 512 CTAs, 4 CTAs/SM -> single wave
    attn_main<<<grid, NT>>>(q, out_attn, out_probs);
}